// round 9
// baseline (speedup 1.0000x reference)
#include <cuda_runtime.h>

#define FULLMASK 0xffffffffu
#define NBLK 128
#define NTHR 1024
typedef unsigned long long u64;
typedef unsigned int u32;

// ---------------- scratch (static __device__, zero-initialized, no allocations) ----------------
static __device__ u32           g_u[86016];        // orderable score bits per anchor
static __device__ unsigned char g_label[86016];    // argmax class per anchor
static __device__ u32           g_h12[3 * 4096];   // 12-bit hist; zeroed in phase C
static __device__ u32           g_h8[3 * 256];     // 8-bit refine hist; zeroed in phase E
static __device__ int           g_B12[3];          // boundary 12-bit bin
static __device__ int           g_C12[3];          // count strictly above boundary bin
static __device__ int           g_T20[3];          // 20-bit threshold (u>>12 >= T20)
static __device__ int           g_candcnt[3];      // reset in phase F
static __device__ u64           g_cand[3 * 2048];
static __device__ u64           g_lkey[3 * 1024];  // per-level sorted global keys
static __device__ float4        g_nbox[3008];
static __device__ unsigned char g_nvalid[3008];
static __device__ int           g_sorder[3008];
static __device__ float4        g_sbox[3008];
static __device__ float         g_sarea[3008];
static __device__ u64           g_validw[48];      // reset in phase I
static __device__ u64           g_supp[3008 * 48]; // rows >= 3000 stay 0 forever
static __device__ int           g_cnt;             // barrier count (returns to 0)
static __device__ volatile int  g_gen;             // barrier generation (monotonic)

__device__ __forceinline__ float sigf(float x) {
    float z = expf(-fabsf(x));
    return (x >= 0.f) ? 1.f / (1.f + z) : z / (1.f + z);
}
__device__ __forceinline__ float clamp01(float v) { return fminf(fmaxf(v, 0.f), 1.f); }

// software global barrier: all NBLK blocks co-resident (grid <= SM count)
__device__ __forceinline__ void gbar() {
    __syncthreads();
    if (threadIdx.x == 0) {
        __threadfence();
        int gen = g_gen;
        if (atomicAdd(&g_cnt, 1) == NBLK - 1) {
            g_cnt = 0;
            __threadfence();
            g_gen = gen + 1;
        } else {
            while (g_gen == gen) { }
        }
        __threadfence();
    }
    __syncthreads();
}

__global__ void __launch_bounds__(NTHR, 1) k_all(
    const float* __restrict__ c0, const float* __restrict__ r0,
    const float* __restrict__ c1, const float* __restrict__ r1,
    const float* __restrict__ c2, const float* __restrict__ r2,
    const float* __restrict__ scales, float* __restrict__ out)
{
    __shared__ u32    sh[4096];
    __shared__ u32    ts[1025];
    __shared__ u64    skey[2048];
    __shared__ float4 s_cbx[64];
    __shared__ float  s_car[64];
    __shared__ u64    s_alive[47], s_S[47], s_R[47], s_kept[47], s_K[47];
    __shared__ int    s_go;

    const int bl = blockIdx.x;
    const int t  = threadIdx.x;
    const int gtid = bl * NTHR + t;
    const int lane = t & 31;
    const int wid  = t >> 5;

    // ---------- Phase A: score + per-block smem 12-bit histogram ----------
    {
        for (int i = t; i < 4096; i += NTHR) sh[i] = 0;
        __syncthreads();
        int l, abase, acount, bfirst, bnum;
        const float* cls;
        if (bl < 98)       { l = 0; abase = 0;     acount = 65536; bfirst = 0;   bnum = 98; cls = c0; }
        else if (bl < 117) { l = 1; abase = 65536; acount = 16384; bfirst = 98;  bnum = 19; cls = c1; }
        else               { l = 2; abase = 81920; acount = 4096;  bfirst = 117; bnum = 11; cls = c2; }
        int gw = (bl - bfirst) * 32 + wid;
        int step = bnum * 32;
        for (int li = gw; li < acount; li += step) {
            const float* row = cls + (size_t)li * 80;
            float v = row[lane];
            int ci = lane;
            float v1 = row[lane + 32];
            if (v1 > v) { v = v1; ci = lane + 32; }
            if (lane < 16) {
                float v2 = row[lane + 64];
                if (v2 > v) { v = v2; ci = lane + 64; }
            }
#pragma unroll
            for (int off = 16; off; off >>= 1) {
                float ov = __shfl_xor_sync(FULLMASK, v, off);
                int oc = __shfl_xor_sync(FULLMASK, ci, off);
                if (ov > v || (ov == v && oc < ci)) { v = ov; ci = oc; }
            }
            if (lane == 0) {
                float s = sigf(v);
                u32 u = __float_as_uint(s);
                u = (u & 0x80000000u) ? ~u : (u | 0x80000000u);
                g_u[abase + li] = u;
                g_label[abase + li] = (unsigned char)ci;
                atomicAdd(&sh[u >> 20], 1u);
            }
        }
        __syncthreads();
        for (int i = t; i < 4096; i += NTHR)
            if (sh[i]) atomicAdd(&g_h12[l * 4096 + i], sh[i]);
    }
    gbar();

    // ---------- Phase B: coarse boundary bin (blocks 0-2) ----------
    if (bl < 3) {
        for (int i = t; i < 4096; i += NTHR) sh[i] = g_h12[bl * 4096 + i];
        __syncthreads();
        u32 s4 = sh[4 * t] + sh[4 * t + 1] + sh[4 * t + 2] + sh[4 * t + 3];
        ts[t] = s4;
        if (t == 0) ts[1024] = 0;
        __syncthreads();
        for (int st = 1; st < 1024; st <<= 1) {
            u32 v = (t + st < 1024) ? ts[t + st] : 0u;
            __syncthreads();
            ts[t] += v;
            __syncthreads();
        }
        u32 sufft = ts[t], suffn = ts[t + 1];
        if (sufft >= 1000u && suffn < 1000u) {
            u32 cnt = suffn;
            int b12 = -1;
#pragma unroll
            for (int c = 3; c >= 0; c--) {
                u32 h = sh[4 * t + c];
                if (b12 < 0) { if (cnt + h >= 1000u) b12 = 4 * t + c; else cnt += h; }
            }
            g_B12[bl] = b12;
            g_C12[bl] = (int)cnt;
        }
    }
    gbar();

    // ---------- Phase C: 8-bit refinement hist; zero h12 ----------
    {
        if (gtid < 12288) g_h12[gtid] = 0;
        if (gtid < 86016) {
            int l = (gtid < 65536) ? 0 : ((gtid < 81920) ? 1 : 2);
            u32 u = g_u[gtid];
            if ((int)(u >> 20) == g_B12[l])
                atomicAdd(&g_h8[l * 256 + ((u >> 12) & 255u)], 1u);
        }
    }
    gbar();

    // ---------- Phase D: refine to 20-bit threshold (blocks 0-2) ----------
    if (bl < 3) {
        if (t < 256) ts[t] = g_h8[bl * 256 + t];
        if (t == 0) ts[256] = 0;
        __syncthreads();
        for (int st = 1; st < 256; st <<= 1) {
            u32 v = (t < 256 && t + st < 256) ? ts[t + st] : 0u;
            __syncthreads();
            if (t < 256) ts[t] += v;
            __syncthreads();
        }
        if (t < 256) {
            int C = g_C12[bl];
            int sufft = (int)ts[t], suffn = (int)ts[t + 1];
            if (sufft + C >= 1000 && suffn + C < 1000)
                g_T20[bl] = (g_B12[bl] << 8) | t;
        }
    }
    gbar();

    // ---------- Phase E: gather candidates; zero h8 ----------
    {
        if (gtid < 768) g_h8[gtid] = 0;
        if (gtid < 86016) {
            int l, base;
            if (gtid < 65536)      { l = 0; base = 0; }
            else if (gtid < 81920) { l = 1; base = 65536; }
            else                   { l = 2; base = 81920; }
            u32 u = g_u[gtid];
            if ((int)(u >> 12) >= g_T20[l]) {
                int p = atomicAdd(&g_candcnt[l], 1);
                if (p < 2048)
                    g_cand[l * 2048 + p] =
                        ((u64)u << 32) | (u32)(0xFFFFFFFFu - (u32)(gtid - base));
            }
        }
    }
    gbar();

    // ---------- Phase F: per-level 2048-key bitonic top-1000 + decode + outputs (blocks 0-2) ----------
    if (bl < 3) {
        int l = bl;
        int K = g_candcnt[l];
        if (K > 2048) K = 2048;
        skey[t]        = (t < K)        ? g_cand[l * 2048 + t]        : 0ull;
        skey[t + 1024] = (t + 1024 < K) ? g_cand[l * 2048 + t + 1024] : 0ull;
        __syncthreads();
        if (t == 0) g_candcnt[l] = 0;
        for (int k = 2; k <= 2048; k <<= 1)
            for (int j = k >> 1; j > 0; j >>= 1) {
#pragma unroll
                for (int it = 0; it < 2; it++) {
                    int i = t + it * 1024;
                    int ixj = i ^ j;
                    if (ixj > i) {
                        u64 a = skey[i], b = skey[ixj];
                        bool up = ((i & k) == 0);
                        if ((a > b) == up) { skey[i] = b; skey[ixj] = a; }
                    }
                }
                __syncthreads();
            }
        if (t < 1000) {
            u64 key = skey[2047 - t];
            u32 u = (u32)(key >> 32);
            u32 local = 0xFFFFFFFFu - (u32)key;
            u32 vb = (u & 0x80000000u) ? (u & 0x7FFFFFFFu) : ~u;
            float score = __uint_as_float(vb);
            int base = (l == 0) ? 0 : ((l == 1) ? 65536 : 81920);
            int logw = (l == 0) ? 8 : ((l == 1) ? 7 : 6);
            float stride = (l == 0) ? 8.f : ((l == 1) ? 16.f : 32.f);
            const float* rp = (l == 0) ? r0 : ((l == 1) ? r1 : r2);
            int lbl = g_label[base + local];
            int x = (int)(local & ((1u << logw) - 1u));
            int y = (int)(local >> logw);
            float ax = (x + 0.5f) * stride, ay = (y + 0.5f) * stride;
            float4 rg = ((const float4*)rp)[local];
            float cx = ax + (sigf(rg.x) * 3.0f - 1.5f);
            float cy = ay + (sigf(rg.y) * 3.0f - 1.5f);
            float sc = scales[l];
            float wv = expf(rg.z * sc), hv = expf(rg.w * sc);
            float x1 = (cx - 0.5f * wv) * stride, y1 = (cy - 0.5f * hv) * stride;
            float x2 = (cx + 0.5f * wv) * stride, y2 = (cy + 0.5f * hv) * stride;
            int o = l * 1000 + t;
            const float inv = 1.0f / 2048.0f;
            out[o * 4 + 0] = clamp01(x1 * inv);
            out[o * 4 + 1] = clamp01(y1 * inv);
            out[o * 4 + 2] = clamp01(x2 * inv);
            out[o * 4 + 3] = clamp01(y2 * inv);
            out[12000 + o] = score;
            out[15000 + o] = (float)lbl;
            float off = (float)lbl * 8192.0f;    // 4 * IMG_W (cross-class separation)
            g_lkey[l * 1024 + t] = ((u64)u << 32) | (0xFFFFFFFFu - (u32)o);
            g_nbox[o] = make_float4(x1 + off, y1 + off, x2 + off, y2 + off);
            g_nvalid[o] = (score >= 0.05f) ? 1 : 0;
        }
    }
    gbar();

    // ---------- Phase G: 3-way merge-by-rank (blocks 0-2) ----------
    if (bl < 3 && t < 1000) {
        int l = bl;
        u64 kg = g_lkey[l * 1024 + t];
        int r = t;
#pragma unroll
        for (int m = 0; m < 3; m++) {
            if (m == l) continue;
            const u64* arr = g_lkey + m * 1024;
            int lo = 0, hi = 1000;
            while (lo < hi) {
                int mid = (lo + hi) >> 1;
                if (arr[mid] > kg) lo = mid + 1; else hi = mid;
            }
            r += lo;
        }
        int o = l * 1000 + t;
        g_sorder[r] = o;
        float4 b = g_nbox[o];
        g_sbox[r] = b;
        g_sarea[r] = (b.z - b.x) * (b.w - b.y);
        if (g_nvalid[o]) atomicOr(&g_validw[r >> 6], 1ull << (r & 63));
    }
    gbar();

    // ---------- Phase H: suppression bitmask matrix ----------
    // block 0 does exactly one tile (it owns phase I); blocks 1..127 cover the rest of 141 tiles
    {
        int tiles[2] = { -1, -1 };
        if (bl == 0) { tiles[0] = 0; }
        else { tiles[0] = bl; if (bl + 127 <= 140) tiles[1] = bl + 127; }
        for (int ti = 0; ti < 2; ti++) {
            int tile = tiles[ti];
            if (tile < 0) break;
            int cb = tile % 47, ch = tile / 47;
            __syncthreads();
            if (t < 64) {
                int j = cb * 64 + t;
                if (j < 3000) { s_cbx[t] = g_sbox[j]; s_car[t] = g_sarea[j]; }
                else          { s_cbx[t] = make_float4(1e30f, 1e30f, 1e30f, 1e30f); s_car[t] = 0.f; }
            }
            __syncthreads();
            int i = ch * 1024 + t;
            if (i < 3000) {
                if ((cb + 1) * 64 <= i) {
                    g_supp[(size_t)i * 48 + cb] = 0ull;
                } else {
                    float4 bi = g_sbox[i];
                    float s = g_sarea[i] + 1e-14f;
                    u64 mask = 0ull;
                    if (cb * 64 > i) {
#pragma unroll 4
                        for (int jj = 0; jj < 64; jj++) {
                            float4 bj = s_cbx[jj];
                            float xx1 = fmaxf(bi.x, bj.x), yy1 = fmaxf(bi.y, bj.y);
                            float xx2 = fminf(bi.z, bj.z), yy2 = fminf(bi.w, bj.w);
                            float w = fmaxf(1e-10f, xx2 - xx1);
                            float h = fmaxf(1e-10f, yy2 - yy1);
                            float inter = w * h;
                            float u = (s + s_car[jj]) - inter;
                            if (inter > 0.6f * u) mask |= (1ull << jj);
                        }
                    } else {
#pragma unroll 4
                        for (int jj = 0; jj < 64; jj++) {
                            float4 bj = s_cbx[jj];
                            float xx1 = fmaxf(bi.x, bj.x), yy1 = fmaxf(bi.y, bj.y);
                            float xx2 = fminf(bi.z, bj.z), yy2 = fminf(bi.w, bj.w);
                            float w = fmaxf(1e-10f, xx2 - xx1);
                            float h = fmaxf(1e-10f, yy2 - yy1);
                            float inter = w * h;
                            float u = (s + s_car[jj]) - inter;
                            if (inter > 0.6f * u && (cb * 64 + jj) > i) mask |= (1ull << jj);
                        }
                    }
                    g_supp[(size_t)i * 48 + cb] = mask;
                }
            }
        }
    }
    gbar();

    // ---------- Phase I: multi-round confirm-kept NMS fixpoint (block 0) ----------
    // Round: S = OR of rows of alive dets; K = alive & ~S are CONFIRMED kept
    // (any j<i suppressing i is non-alive: kept j => i already removed; removed j => j not greedy-kept).
    // Remove K's rows; repeat. >=1 det confirms per round => terminates; sparse graph => ~2-4 rounds.
    if (bl != 0) return;
    if (t < 47) {
        u64 valid = g_validw[t];
        s_alive[t] = valid;          // alive = valid, undecided
        s_kept[t] = 0ull;
        g_validw[t] = 0ull;          // clean for next replay
    }
    __syncthreads();
    {
        const int f = t % 47;                 // column word this thread accumulates
        const int chunk = t / 47;             // det chunk 0..20 (987 active threads)
        const bool act = (t < 987);
        const int i0 = chunk * 143;
        const int ilimF = (f + 1) * 64;       // rows i >= ilimF have zero word f
        while (true) {
            if (t < 47) { s_S[t] = 0ull; s_R[t] = 0ull; }
            if (t == 0) s_go = 0;
            __syncthreads();
            // pass 1: S = OR of alive rows (bit-iterate alive words in my chunk)
            if (act) {
                u64 acc = 0ull;
                int hiC = min(min(i0 + 143, 3000), ilimF);
                for (int w = i0 >> 6; w * 64 < hiC; w++) {
                    int lo = max(i0, w * 64), hi = min(hiC, (w + 1) * 64);
                    if (hi <= lo) continue;
                    int nb = hi - lo;
                    u64 m = s_alive[w] >> (lo - w * 64);
                    if (nb < 64) m &= (1ull << nb) - 1ull;
                    while (m) {
                        int b = __ffsll((long long)m) - 1;
                        m &= m - 1ull;
                        acc |= g_supp[(size_t)(lo + b) * 48 + f];
                    }
                }
                if (acc) atomicOr(&s_S[f], acc);
            }
            __syncthreads();
            if (t < 47) {
                u64 K = s_alive[t] & ~s_S[t];
                s_K[t] = K;
                s_kept[t] |= K;
                s_alive[t] &= ~K;
            }
            __syncthreads();
            // pass 2: removals from confirmed rows
            if (act) {
                u64 acc = 0ull;
                int hiC = min(min(i0 + 143, 3000), ilimF);
                for (int w = i0 >> 6; w * 64 < hiC; w++) {
                    int lo = max(i0, w * 64), hi = min(hiC, (w + 1) * 64);
                    if (hi <= lo) continue;
                    int nb = hi - lo;
                    u64 m = s_K[w] >> (lo - w * 64);
                    if (nb < 64) m &= (1ull << nb) - 1ull;
                    while (m) {
                        int b = __ffsll((long long)m) - 1;
                        m &= m - 1ull;
                        acc |= g_supp[(size_t)(lo + b) * 48 + f];
                    }
                }
                if (acc) atomicOr(&s_R[f], acc);
            }
            __syncthreads();
            if (t < 47) {
                s_alive[t] &= ~s_R[t];
                if (s_alive[t]) s_go = 1;
            }
            __syncthreads();
            if (!s_go) break;
        }
    }
    // ---------- outputs ----------
    for (int r = t; r < 3000; r += NTHR) {
        int kept = (int)((s_kept[r >> 6] >> (r & 63)) & 1ull);
        out[18000 + g_sorder[r]] = kept ? 1.0f : 0.0f;
    }
}

// ---------------- launch ----------------
extern "C" void kernel_launch(void* const* d_in, const int* in_sizes, int n_in,
                              void* d_out, int out_size) {
    (void)in_sizes; (void)n_in; (void)out_size;
    const float* c0 = (const float*)d_in[0];
    const float* r0 = (const float*)d_in[1];
    const float* c1 = (const float*)d_in[2];
    const float* r1 = (const float*)d_in[3];
    const float* c2 = (const float*)d_in[4];
    const float* r2 = (const float*)d_in[5];
    const float* sc = (const float*)d_in[6];
    float* out = (float*)d_out;

    k_all<<<NBLK, NTHR>>>(c0, r0, c1, r1, c2, r2, sc, out);
}

// round 12
// speedup vs baseline: 1.9271x; 1.9271x over previous
#include <cuda_runtime.h>

#define FULLMASK 0xffffffffu
#define NBLK 128
#define NTHR 1024
typedef unsigned long long u64;
typedef unsigned int u32;

// ---------------- scratch (static __device__, zero-initialized, no allocations) ----------------
static __device__ u32           g_u[86016];        // orderable score bits per anchor
static __device__ unsigned char g_label[86016];    // argmax class per anchor
static __device__ u32           g_h12[3 * 4096];   // 12-bit hist; zeroed in phase C
static __device__ u32           g_h8[3 * 256];     // 8-bit refine hist; zeroed in phase E
static __device__ int           g_B12[3];          // boundary 12-bit bin
static __device__ int           g_C12[3];          // count strictly above boundary bin
static __device__ int           g_T20[3];          // 20-bit threshold (u>>12 >= T20)
static __device__ int           g_candcnt[3];      // reset in phase F
static __device__ u64           g_cand[3 * 2048];
static __device__ u64           g_lkey[3 * 1024];  // per-level sorted global keys
static __device__ float4        g_nbox[3008];
static __device__ unsigned char g_nvalid[3008];
static __device__ int           g_sorder[3008];
static __device__ float4        g_sbox[3008];
static __device__ float         g_sarea[3008];
static __device__ u64           g_validw[48];      // zeroed by block 0 at end of phase I
static __device__ u64           g_S[47];           // round-1 suppression OR; re-zeroed after use
static __device__ u64           g_R[47];           // round-1 removal OR; re-zeroed after use
static __device__ u64           g_supp[3008 * 48]; // rows >= 3000 stay 0 forever
static __device__ int           g_cnt;             // barrier count (returns to 0)
static __device__ volatile int  g_gen;             // barrier generation (monotonic)

__device__ __forceinline__ float sigf(float x) {
    float z = expf(-fabsf(x));
    return (x >= 0.f) ? 1.f / (1.f + z) : z / (1.f + z);
}
__device__ __forceinline__ float clamp01(float v) { return fminf(fmaxf(v, 0.f), 1.f); }

// software global barrier: all NBLK blocks co-resident (grid <= SM count)
__device__ __forceinline__ void gbar() {
    __syncthreads();
    if (threadIdx.x == 0) {
        __threadfence();
        int gen = g_gen;
        if (atomicAdd(&g_cnt, 1) == NBLK - 1) {
            g_cnt = 0;
            __threadfence();
            g_gen = gen + 1;
        } else {
            while (g_gen == gen) { }
        }
        __threadfence();
    }
    __syncthreads();
}

__global__ void __launch_bounds__(NTHR, 1) k_all(
    const float* __restrict__ c0, const float* __restrict__ r0,
    const float* __restrict__ c1, const float* __restrict__ r1,
    const float* __restrict__ c2, const float* __restrict__ r2,
    const float* __restrict__ scales, float* __restrict__ out)
{
    __shared__ u32    sh[4096];          // hist / alive-list scratch
    __shared__ u32    ts[1025];
    __shared__ u64    skey[2048];
    __shared__ float4 s_cbx[64];
    __shared__ float  s_car[64];
    __shared__ u64    s_valid[47], s_S[47], s_R[47], s_K[47], s_alive[47], s_kept[47];
    __shared__ int    s_cnt;

    const int bl = blockIdx.x;
    const int t  = threadIdx.x;
    const int gtid = bl * NTHR + t;
    const int lane = t & 31;
    const int wid  = t >> 5;

    // ---------- Phase A: score + per-block smem 12-bit histogram ----------
    {
        for (int i = t; i < 4096; i += NTHR) sh[i] = 0;
        __syncthreads();
        int l, abase, acount, bfirst, bnum;
        const float* cls;
        if (bl < 98)       { l = 0; abase = 0;     acount = 65536; bfirst = 0;   bnum = 98; cls = c0; }
        else if (bl < 117) { l = 1; abase = 65536; acount = 16384; bfirst = 98;  bnum = 19; cls = c1; }
        else               { l = 2; abase = 81920; acount = 4096;  bfirst = 117; bnum = 11; cls = c2; }
        int gw = (bl - bfirst) * 32 + wid;
        int step = bnum * 32;
        for (int li = gw; li < acount; li += step) {
            const float* row = cls + (size_t)li * 80;
            float v = row[lane];
            int ci = lane;
            float v1 = row[lane + 32];
            if (v1 > v) { v = v1; ci = lane + 32; }
            if (lane < 16) {
                float v2 = row[lane + 64];
                if (v2 > v) { v = v2; ci = lane + 64; }
            }
#pragma unroll
            for (int off = 16; off; off >>= 1) {
                float ov = __shfl_xor_sync(FULLMASK, v, off);
                int oc = __shfl_xor_sync(FULLMASK, ci, off);
                if (ov > v || (ov == v && oc < ci)) { v = ov; ci = oc; }
            }
            if (lane == 0) {
                float s = sigf(v);
                u32 u = __float_as_uint(s);
                u = (u & 0x80000000u) ? ~u : (u | 0x80000000u);
                g_u[abase + li] = u;
                g_label[abase + li] = (unsigned char)ci;
                atomicAdd(&sh[u >> 20], 1u);
            }
        }
        __syncthreads();
        for (int i = t; i < 4096; i += NTHR)
            if (sh[i]) atomicAdd(&g_h12[l * 4096 + i], sh[i]);
    }
    gbar();

    // ---------- Phase B: coarse boundary bin (blocks 0-2) ----------
    if (bl < 3) {
        for (int i = t; i < 4096; i += NTHR) sh[i] = g_h12[bl * 4096 + i];
        __syncthreads();
        u32 s4 = sh[4 * t] + sh[4 * t + 1] + sh[4 * t + 2] + sh[4 * t + 3];
        ts[t] = s4;
        if (t == 0) ts[1024] = 0;
        __syncthreads();
        for (int st = 1; st < 1024; st <<= 1) {
            u32 v = (t + st < 1024) ? ts[t + st] : 0u;
            __syncthreads();
            ts[t] += v;
            __syncthreads();
        }
        u32 sufft = ts[t], suffn = ts[t + 1];
        if (sufft >= 1000u && suffn < 1000u) {
            u32 cnt = suffn;
            int b12 = -1;
#pragma unroll
            for (int c = 3; c >= 0; c--) {
                u32 h = sh[4 * t + c];
                if (b12 < 0) { if (cnt + h >= 1000u) b12 = 4 * t + c; else cnt += h; }
            }
            g_B12[bl] = b12;
            g_C12[bl] = (int)cnt;
        }
    }
    gbar();

    // ---------- Phase C: 8-bit refinement hist; zero h12 ----------
    {
        if (gtid < 12288) g_h12[gtid] = 0;
        if (gtid < 86016) {
            int l = (gtid < 65536) ? 0 : ((gtid < 81920) ? 1 : 2);
            u32 u = g_u[gtid];
            if ((int)(u >> 20) == g_B12[l])
                atomicAdd(&g_h8[l * 256 + ((u >> 12) & 255u)], 1u);
        }
    }
    gbar();

    // ---------- Phase D: refine to 20-bit threshold (blocks 0-2) ----------
    if (bl < 3) {
        if (t < 256) ts[t] = g_h8[bl * 256 + t];
        if (t == 0) ts[256] = 0;
        __syncthreads();
        for (int st = 1; st < 256; st <<= 1) {
            u32 v = (t < 256 && t + st < 256) ? ts[t + st] : 0u;
            __syncthreads();
            if (t < 256) ts[t] += v;
            __syncthreads();
        }
        if (t < 256) {
            int C = g_C12[bl];
            int sufft = (int)ts[t], suffn = (int)ts[t + 1];
            if (sufft + C >= 1000 && suffn + C < 1000)
                g_T20[bl] = (g_B12[bl] << 8) | t;
        }
    }
    gbar();

    // ---------- Phase E: gather candidates; zero h8 / g_S / g_R ----------
    {
        if (gtid < 768) g_h8[gtid] = 0;
        if (gtid >= 768 && gtid < 815) g_S[gtid - 768] = 0ull;   // belt-and-braces
        if (gtid >= 815 && gtid < 862) g_R[gtid - 815] = 0ull;
        if (gtid < 86016) {
            int l, base;
            if (gtid < 65536)      { l = 0; base = 0; }
            else if (gtid < 81920) { l = 1; base = 65536; }
            else                   { l = 2; base = 81920; }
            u32 u = g_u[gtid];
            if ((int)(u >> 12) >= g_T20[l]) {
                int p = atomicAdd(&g_candcnt[l], 1);
                if (p < 2048)
                    g_cand[l * 2048 + p] =
                        ((u64)u << 32) | (u32)(0xFFFFFFFFu - (u32)(gtid - base));
            }
        }
    }
    gbar();

    // ---------- Phase F: per-level 2048-key bitonic top-1000 + decode + outputs (blocks 0-2) ----------
    if (bl < 3) {
        int l = bl;
        int K = g_candcnt[l];
        if (K > 2048) K = 2048;
        skey[t]        = (t < K)        ? g_cand[l * 2048 + t]        : 0ull;
        skey[t + 1024] = (t + 1024 < K) ? g_cand[l * 2048 + t + 1024] : 0ull;
        __syncthreads();
        if (t == 0) g_candcnt[l] = 0;
        for (int k = 2; k <= 2048; k <<= 1)
            for (int j = k >> 1; j > 0; j >>= 1) {
#pragma unroll
                for (int it = 0; it < 2; it++) {
                    int i = t + it * 1024;
                    int ixj = i ^ j;
                    if (ixj > i) {
                        u64 a = skey[i], b = skey[ixj];
                        bool up = ((i & k) == 0);
                        if ((a > b) == up) { skey[i] = b; skey[ixj] = a; }
                    }
                }
                __syncthreads();
            }
        if (t < 1000) {
            u64 key = skey[2047 - t];
            u32 u = (u32)(key >> 32);
            u32 local = 0xFFFFFFFFu - (u32)key;
            u32 vb = (u & 0x80000000u) ? (u & 0x7FFFFFFFu) : ~u;
            float score = __uint_as_float(vb);
            int base = (l == 0) ? 0 : ((l == 1) ? 65536 : 81920);
            int logw = (l == 0) ? 8 : ((l == 1) ? 7 : 6);
            float stride = (l == 0) ? 8.f : ((l == 1) ? 16.f : 32.f);
            const float* rp = (l == 0) ? r0 : ((l == 1) ? r1 : r2);
            int lbl = g_label[base + local];
            int x = (int)(local & ((1u << logw) - 1u));
            int y = (int)(local >> logw);
            float ax = (x + 0.5f) * stride, ay = (y + 0.5f) * stride;
            float4 rg = ((const float4*)rp)[local];
            float cx = ax + (sigf(rg.x) * 3.0f - 1.5f);
            float cy = ay + (sigf(rg.y) * 3.0f - 1.5f);
            float sc = scales[l];
            float wv = expf(rg.z * sc), hv = expf(rg.w * sc);
            float x1 = (cx - 0.5f * wv) * stride, y1 = (cy - 0.5f * hv) * stride;
            float x2 = (cx + 0.5f * wv) * stride, y2 = (cy + 0.5f * hv) * stride;
            int o = l * 1000 + t;
            const float inv = 1.0f / 2048.0f;
            out[o * 4 + 0] = clamp01(x1 * inv);
            out[o * 4 + 1] = clamp01(y1 * inv);
            out[o * 4 + 2] = clamp01(x2 * inv);
            out[o * 4 + 3] = clamp01(y2 * inv);
            out[12000 + o] = score;
            out[15000 + o] = (float)lbl;
            float off = (float)lbl * 8192.0f;    // 4 * IMG_W (cross-class separation)
            g_lkey[l * 1024 + t] = ((u64)u << 32) | (0xFFFFFFFFu - (u32)o);
            g_nbox[o] = make_float4(x1 + off, y1 + off, x2 + off, y2 + off);
            g_nvalid[o] = (score >= 0.05f) ? 1 : 0;
        }
    }
    gbar();

    // ---------- Phase G: 3-way merge-by-rank (blocks 0-2) ----------
    if (bl < 3 && t < 1000) {
        int l = bl;
        u64 kg = g_lkey[l * 1024 + t];
        int r = t;
#pragma unroll
        for (int m = 0; m < 3; m++) {
            if (m == l) continue;
            const u64* arr = g_lkey + m * 1024;
            int lo = 0, hi = 1000;
            while (lo < hi) {
                int mid = (lo + hi) >> 1;
                if (arr[mid] > kg) lo = mid + 1; else hi = mid;
            }
            r += lo;
        }
        int o = l * 1000 + t;
        g_sorder[r] = o;
        float4 b = g_nbox[o];
        g_sbox[r] = b;
        g_sarea[r] = (b.z - b.x) * (b.w - b.y);
        if (g_nvalid[o]) atomicOr(&g_validw[r >> 6], 1ull << (r & 63));
    }
    gbar();

    // ---------- Phase H: suppression bitmask matrix (141 tiles over 128 blocks) ----------
    for (int tile = bl; tile < 141; tile += NBLK) {
        int cb = tile % 47, ch = tile / 47;
        __syncthreads();
        if (t < 64) {
            int j = cb * 64 + t;
            if (j < 3000) { s_cbx[t] = g_sbox[j]; s_car[t] = g_sarea[j]; }
            else          { s_cbx[t] = make_float4(1e30f, 1e30f, 1e30f, 1e30f); s_car[t] = 0.f; }
        }
        __syncthreads();
        int i = ch * 1024 + t;
        if (i < 3000) {
            if ((cb + 1) * 64 <= i) {
                g_supp[(size_t)i * 48 + cb] = 0ull;
            } else {
                float4 bi = g_sbox[i];
                float s = g_sarea[i] + 1e-14f;
                u64 mask = 0ull;
                if (cb * 64 > i) {
#pragma unroll 4
                    for (int jj = 0; jj < 64; jj++) {
                        float4 bj = s_cbx[jj];
                        float xx1 = fmaxf(bi.x, bj.x), yy1 = fmaxf(bi.y, bj.y);
                        float xx2 = fminf(bi.z, bj.z), yy2 = fminf(bi.w, bj.w);
                        float w = fmaxf(1e-10f, xx2 - xx1);
                        float h = fmaxf(1e-10f, yy2 - yy1);
                        float inter = w * h;
                        float u = (s + s_car[jj]) - inter;
                        if (inter > 0.6f * u) mask |= (1ull << jj);
                    }
                } else {
#pragma unroll 4
                    for (int jj = 0; jj < 64; jj++) {
                        float4 bj = s_cbx[jj];
                        float xx1 = fmaxf(bi.x, bj.x), yy1 = fmaxf(bi.y, bj.y);
                        float xx2 = fminf(bi.z, bj.z), yy2 = fminf(bi.w, bj.w);
                        float w = fmaxf(1e-10f, xx2 - xx1);
                        float h = fmaxf(1e-10f, yy2 - yy1);
                        float inter = w * h;
                        float u = (s + s_car[jj]) - inter;
                        if (inter > 0.6f * u && (cb * 64 + jj) > i) mask |= (1ull << jj);
                    }
                }
                g_supp[(size_t)i * 48 + cb] = mask;
            }
        }
    }
    gbar();

    // ---------- Phase I: NMS fixpoint ----------
    // Round 1 is dense and chip-wide: S = OR of rows of all valid dets (141,376 coalesced
    // (row,word) loads over 131,072 threads), K = valid & ~S confirmed kept (no valid
    // predecessor suppresses them), R = OR of rows of K. Follow-up rounds (alive small)
    // run on block 0 with explicit alive/kept lists.
    if (t < 47) { s_valid[t] = g_validw[t]; s_S[t] = 0ull; }
    __syncthreads();
    // pass 1: dense S
    for (int idx = gtid; idx < 141376; idx += NBLK * NTHR) {
        int i = idx / 47, f = idx - i * 47;
        if ((s_valid[i >> 6] >> (i & 63)) & 1ull) {
            u64 v = g_supp[(size_t)i * 48 + f];
            if (v) atomicOr(&s_S[f], v);
        }
    }
    __syncthreads();
    if (t < 47 && s_S[t]) atomicOr(&g_S[t], s_S[t]);
    gbar();
    // pass 2: dense R over K = valid & ~S
    if (t < 47) { s_K[t] = s_valid[t] & ~g_S[t]; s_R[t] = 0ull; }
    __syncthreads();
    for (int idx = gtid; idx < 141376; idx += NBLK * NTHR) {
        int i = idx / 47, f = idx - i * 47;
        if ((s_K[i >> 6] >> (i & 63)) & 1ull) {
            u64 v = g_supp[(size_t)i * 48 + f];
            if (v) atomicOr(&s_R[f], v);
        }
    }
    __syncthreads();
    if (t < 47 && s_R[t]) atomicOr(&g_R[t], s_R[t]);
    gbar();
    if (bl != 0) return;

    // block 0: finish fixpoint solo
    if (t < 47) {
        s_kept[t] = s_K[t];
        s_alive[t] = s_valid[t] & ~s_K[t] & ~g_R[t];
        g_S[t] = 0ull;                      // clean for next replay
        g_R[t] = 0ull;
        g_validw[t] = 0ull;
    }
    __syncthreads();
    {
        int* list = (int*)sh;               // reuse hist scratch as index list
        while (true) {
            if (t == 0) s_cnt = 0;
            if (t < 47) s_S[t] = 0ull;
            __syncthreads();
            if (t < 47) {
                u64 m = s_alive[t];
                while (m) {
                    int b = __ffsll((long long)m) - 1;
                    m &= m - 1ull;
                    list[atomicAdd(&s_cnt, 1)] = t * 64 + b;
                }
            }
            __syncthreads();
            int n = s_cnt;
            if (n == 0) break;
            for (int p = t; p < n * 47; p += NTHR) {
                int k = p / 47, f = p - k * 47;
                u64 v = g_supp[(size_t)list[k] * 48 + f];
                if (v) atomicOr(&s_S[f], v);
            }
            __syncthreads();
            if (t == 0) s_cnt = 0;
            if (t < 47) {
                u64 K = s_alive[t] & ~s_S[t];
                s_K[t] = K;
                s_kept[t] |= K;
                s_alive[t] &= ~K;
                s_R[t] = 0ull;
            }
            __syncthreads();
            if (t < 47) {
                u64 m = s_K[t];
                while (m) {
                    int b = __ffsll((long long)m) - 1;
                    m &= m - 1ull;
                    list[atomicAdd(&s_cnt, 1)] = t * 64 + b;
                }
            }
            __syncthreads();
            int nk = s_cnt;
            for (int p = t; p < nk * 47; p += NTHR) {
                int k = p / 47, f = p - k * 47;
                u64 v = g_supp[(size_t)list[k] * 48 + f];
                if (v) atomicOr(&s_R[f], v);
            }
            __syncthreads();
            if (t < 47) s_alive[t] &= ~s_R[t];
            __syncthreads();
        }
    }
    // ---------- outputs ----------
    for (int r = t; r < 3000; r += NTHR) {
        int kept = (int)((s_kept[r >> 6] >> (r & 63)) & 1ull);
        out[18000 + g_sorder[r]] = kept ? 1.0f : 0.0f;
    }
}

// ---------------- launch ----------------
extern "C" void kernel_launch(void* const* d_in, const int* in_sizes, int n_in,
                              void* d_out, int out_size) {
    (void)in_sizes; (void)n_in; (void)out_size;
    const float* c0 = (const float*)d_in[0];
    const float* r0 = (const float*)d_in[1];
    const float* c1 = (const float*)d_in[2];
    const float* r1 = (const float*)d_in[3];
    const float* c2 = (const float*)d_in[4];
    const float* r2 = (const float*)d_in[5];
    const float* sc = (const float*)d_in[6];
    float* out = (float*)d_out;

    k_all<<<NBLK, NTHR>>>(c0, r0, c1, r1, c2, r2, sc, out);
}

// round 17
// speedup vs baseline: 2.4047x; 1.2478x over previous
#include <cuda_runtime.h>

#define FULLMASK 0xffffffffu
#define NBLK 148
#define NTHR 1024
typedef unsigned long long u64;
typedef unsigned int u32;

// ---------------- scratch (static __device__, zero-initialized, no allocations) ----------------
static __device__ u32           g_u[86016];        // orderable score bits per anchor
static __device__ unsigned char g_label[86016];    // argmax class per anchor
static __device__ u32           g_h12[3 * 4096];   // 12-bit hist; zeroed in phase B'
static __device__ int           g_T20[3];          // 20-bit threshold (u>>12 >= T20)
static __device__ int           g_candcnt[3];      // reset in phase F
static __device__ u64           g_cand[3 * 2048];
static __device__ u64           g_lkey[3 * 1024];  // per-level sorted global keys
static __device__ float4        g_nbox[3008];
static __device__ unsigned char g_nvalid[3008];
static __device__ int           g_sorder[3008];
static __device__ float4        g_sbox[3008];
static __device__ float         g_sarea[3008];
static __device__ u64           g_validw[48];      // zeroed by block 0 at end of phase I
static __device__ u64           g_S[47];           // round-1 suppression OR; re-zeroed after use
static __device__ u64           g_R[47];           // round-1 removal OR; re-zeroed after use
static __device__ u64           g_supp[3008 * 48]; // rows >= 3000 stay 0 forever
static __device__ int           g_cnt;             // barrier count (returns to 0)
static __device__ volatile int  g_gen;             // barrier generation (monotonic)

__device__ __forceinline__ float sigf(float x) {
    float z = expf(-fabsf(x));
    return (x >= 0.f) ? 1.f / (1.f + z) : z / (1.f + z);
}
__device__ __forceinline__ float clamp01(float v) { return fminf(fmaxf(v, 0.f), 1.f); }

// software global barrier: all NBLK blocks co-resident (grid <= SM count)
__device__ __forceinline__ void gbar() {
    __syncthreads();
    if (threadIdx.x == 0) {
        __threadfence();
        int gen = g_gen;
        if (atomicAdd(&g_cnt, 1) == NBLK - 1) {
            g_cnt = 0;
            __threadfence();
            g_gen = gen + 1;
        } else {
            while (g_gen == gen) { }
        }
        __threadfence();
    }
    __syncthreads();
}

__global__ void __launch_bounds__(NTHR, 1) k_all(
    const float* __restrict__ c0, const float* __restrict__ r0,
    const float* __restrict__ c1, const float* __restrict__ r1,
    const float* __restrict__ c2, const float* __restrict__ r2,
    const float* __restrict__ scales, float* __restrict__ out)
{
    __shared__ u32    sh[4096];          // hist / list scratch
    __shared__ u32    ts[1025];
    __shared__ u64    skey[2048];
    __shared__ float4 s_cbx[64];
    __shared__ float  s_car[64];
    __shared__ u64    s_valid[47], s_S[47], s_R[47], s_K[47], s_alive[47], s_kept[47];
    __shared__ int    s_cnt, s_b12, s_c12;

    const int bl = blockIdx.x;
    const int t  = threadIdx.x;
    const int gtid = bl * NTHR + t;
    const int lane = t & 31;
    const int wid  = t >> 5;

    // ---------- Phase A: score + per-block smem 12-bit histogram ----------
    {
        for (int i = t; i < 4096; i += NTHR) sh[i] = 0;
        __syncthreads();
        int l, abase, acount, bfirst, bnum;
        const float* cls;
        if (bl < 113)      { l = 0; abase = 0;     acount = 65536; bfirst = 0;   bnum = 113; cls = c0; }
        else if (bl < 141) { l = 1; abase = 65536; acount = 16384; bfirst = 113; bnum = 28;  cls = c1; }
        else               { l = 2; abase = 81920; acount = 4096;  bfirst = 141; bnum = 7;   cls = c2; }
        int gw = (bl - bfirst) * 32 + wid;
        int step = bnum * 32;
        for (int li = gw; li < acount; li += step) {
            const float* row = cls + (size_t)li * 80;
            float v = row[lane];
            int ci = lane;
            float v1 = row[lane + 32];
            if (v1 > v) { v = v1; ci = lane + 32; }
            if (lane < 16) {
                float v2 = row[lane + 64];
                if (v2 > v) { v = v2; ci = lane + 64; }
            }
#pragma unroll
            for (int off = 16; off; off >>= 1) {
                float ov = __shfl_xor_sync(FULLMASK, v, off);
                int oc = __shfl_xor_sync(FULLMASK, ci, off);
                if (ov > v || (ov == v && oc < ci)) { v = ov; ci = oc; }
            }
            if (lane == 0) {
                float s = sigf(v);
                u32 u = __float_as_uint(s);
                u = (u & 0x80000000u) ? ~u : (u | 0x80000000u);
                g_u[abase + li] = u;
                g_label[abase + li] = (unsigned char)ci;
                atomicAdd(&sh[u >> 20], 1u);
            }
        }
        __syncthreads();
        for (int i = t; i < 4096; i += NTHR)
            if (sh[i]) atomicAdd(&g_h12[l * 4096 + i], sh[i]);
    }
    gbar();

    // ---------- Phase B': fused coarse + refine threshold (blocks 0-2) ----------
    if (bl < 3) {
        const int l = bl;
        const int acount = (l == 0) ? 65536 : ((l == 1) ? 16384 : 4096);
        const u32* U = g_u + ((l == 0) ? 0 : ((l == 1) ? 65536 : 81920));
        // coarse: copy h12, suffix-sum, find boundary bin b12 + count above (c12)
        for (int i = t; i < 4096; i += NTHR) sh[i] = g_h12[l * 4096 + i];
        __syncthreads();
        for (int i = t; i < 4096; i += NTHR) g_h12[l * 4096 + i] = 0;  // clean for replay
        u32 s4 = sh[4 * t] + sh[4 * t + 1] + sh[4 * t + 2] + sh[4 * t + 3];
        ts[t] = s4;
        if (t == 0) ts[1024] = 0;
        __syncthreads();
        for (int st = 1; st < 1024; st <<= 1) {
            u32 v = (t + st < 1024) ? ts[t + st] : 0u;
            __syncthreads();
            ts[t] += v;
            __syncthreads();
        }
        {
            u32 sufft = ts[t], suffn = ts[t + 1];
            if (sufft >= 1000u && suffn < 1000u) {
                u32 cnt = suffn;
                int b12 = -1;
#pragma unroll
                for (int c = 3; c >= 0; c--) {
                    u32 h = sh[4 * t + c];
                    if (b12 < 0) { if (cnt + h >= 1000u) b12 = 4 * t + c; else cnt += h; }
                }
                s_b12 = b12;
                s_c12 = (int)cnt;
            }
        }
        __syncthreads();
        const int b12 = s_b12;
        // refine: 8-bit hist of boundary-bin anchors (rescan this level's g_u, coalesced)
        if (t < 256) sh[t] = 0;
        __syncthreads();
        for (int i = t; i < acount; i += NTHR) {
            u32 u = U[i];
            if ((int)(u >> 20) == b12) atomicAdd(&sh[(u >> 12) & 255u], 1u);
        }
        __syncthreads();
        if (t < 256) ts[t] = sh[t];
        if (t == 0) ts[256] = 0;
        __syncthreads();
        for (int st = 1; st < 256; st <<= 1) {
            u32 v = (t < 256 && t + st < 256) ? ts[t + st] : 0u;
            __syncthreads();
            if (t < 256) ts[t] += v;
            __syncthreads();
        }
        if (t < 256) {
            int C = s_c12;
            int sufft = (int)ts[t], suffn = (int)ts[t + 1];
            if (sufft + C >= 1000 && suffn + C < 1000)
                g_T20[l] = (b12 << 8) | t;
        }
    }
    gbar();

    // ---------- Phase E: gather candidates; zero g_S / g_R ----------
    {
        if (gtid >= 86016 && gtid < 86063) g_S[gtid - 86016] = 0ull;
        if (gtid >= 86063 && gtid < 86110) g_R[gtid - 86063] = 0ull;
        if (gtid < 86016) {
            int l, base;
            if (gtid < 65536)      { l = 0; base = 0; }
            else if (gtid < 81920) { l = 1; base = 65536; }
            else                   { l = 2; base = 81920; }
            u32 u = g_u[gtid];
            if ((int)(u >> 12) >= g_T20[l]) {
                int p = atomicAdd(&g_candcnt[l], 1);
                if (p < 2048)
                    g_cand[l * 2048 + p] =
                        ((u64)u << 32) | (u32)(0xFFFFFFFFu - (u32)(gtid - base));
            }
        }
    }
    gbar();

    // ---------- Phase F: per-level bitonic top-1000 (1024 or 2048 keys) + decode + outputs ----------
    if (bl < 3) {
        int l = bl;
        int K = g_candcnt[l];
        if (K > 2048) K = 2048;
        int n = (K <= 1024) ? 1024 : 2048;
        for (int i = t; i < n; i += NTHR) skey[i] = (i < K) ? g_cand[l * 2048 + i] : 0ull;
        __syncthreads();
        if (t == 0) g_candcnt[l] = 0;
        for (int k = 2; k <= n; k <<= 1)
            for (int j = k >> 1; j > 0; j >>= 1) {
                for (int i = t; i < n; i += NTHR) {
                    int ixj = i ^ j;
                    if (ixj > i) {
                        u64 a = skey[i], b = skey[ixj];
                        bool up = ((i & k) == 0);
                        if ((a > b) == up) { skey[i] = b; skey[ixj] = a; }
                    }
                }
                __syncthreads();
            }
        if (t < 1000) {
            u64 key = skey[n - 1 - t];
            u32 u = (u32)(key >> 32);
            u32 local = 0xFFFFFFFFu - (u32)key;
            u32 vb = (u & 0x80000000u) ? (u & 0x7FFFFFFFu) : ~u;
            float score = __uint_as_float(vb);
            int base = (l == 0) ? 0 : ((l == 1) ? 65536 : 81920);
            int logw = (l == 0) ? 8 : ((l == 1) ? 7 : 6);
            float stride = (l == 0) ? 8.f : ((l == 1) ? 16.f : 32.f);
            const float* rp = (l == 0) ? r0 : ((l == 1) ? r1 : r2);
            int lbl = g_label[base + local];
            int x = (int)(local & ((1u << logw) - 1u));
            int y = (int)(local >> logw);
            float ax = (x + 0.5f) * stride, ay = (y + 0.5f) * stride;
            float4 rg = ((const float4*)rp)[local];
            float cx = ax + (sigf(rg.x) * 3.0f - 1.5f);
            float cy = ay + (sigf(rg.y) * 3.0f - 1.5f);
            float sc = scales[l];
            float wv = expf(rg.z * sc), hv = expf(rg.w * sc);
            float x1 = (cx - 0.5f * wv) * stride, y1 = (cy - 0.5f * hv) * stride;
            float x2 = (cx + 0.5f * wv) * stride, y2 = (cy + 0.5f * hv) * stride;
            int o = l * 1000 + t;
            const float inv = 1.0f / 2048.0f;
            out[o * 4 + 0] = clamp01(x1 * inv);
            out[o * 4 + 1] = clamp01(y1 * inv);
            out[o * 4 + 2] = clamp01(x2 * inv);
            out[o * 4 + 3] = clamp01(y2 * inv);
            out[12000 + o] = score;
            out[15000 + o] = (float)lbl;
            float off = (float)lbl * 8192.0f;    // 4 * IMG_W (cross-class separation)
            g_lkey[l * 1024 + t] = ((u64)u << 32) | (0xFFFFFFFFu - (u32)o);
            g_nbox[o] = make_float4(x1 + off, y1 + off, x2 + off, y2 + off);
            g_nvalid[o] = (score >= 0.05f) ? 1 : 0;
        }
    }
    gbar();

    // ---------- Phase G: 3-way merge-by-rank (blocks 0-2) ----------
    if (bl < 3 && t < 1000) {
        int l = bl;
        u64 kg = g_lkey[l * 1024 + t];
        int r = t;
#pragma unroll
        for (int m = 0; m < 3; m++) {
            if (m == l) continue;
            const u64* arr = g_lkey + m * 1024;
            int lo = 0, hi = 1000;
            while (lo < hi) {
                int mid = (lo + hi) >> 1;
                if (arr[mid] > kg) lo = mid + 1; else hi = mid;
            }
            r += lo;
        }
        int o = l * 1000 + t;
        g_sorder[r] = o;
        float4 b = g_nbox[o];
        g_sbox[r] = b;
        g_sarea[r] = (b.z - b.x) * (b.w - b.y);
        if (g_nvalid[o]) atomicOr(&g_validw[r >> 6], 1ull << (r & 63));
    }
    gbar();

    // ---------- Phase H: suppression bitmask matrix (141 tiles, <=1 per block) ----------
    if (bl < 141) {
        int cb = bl % 47, ch = bl / 47;
        if (t < 64) {
            int j = cb * 64 + t;
            if (j < 3000) { s_cbx[t] = g_sbox[j]; s_car[t] = g_sarea[j]; }
            else          { s_cbx[t] = make_float4(1e30f, 1e30f, 1e30f, 1e30f); s_car[t] = 0.f; }
        }
        __syncthreads();
        int i = ch * 1024 + t;
        if (i < 3000) {
            if ((cb + 1) * 64 <= i) {
                g_supp[(size_t)i * 48 + cb] = 0ull;
            } else {
                float4 bi = g_sbox[i];
                float s = g_sarea[i] + 1e-14f;
                u64 mask = 0ull;
                if (cb * 64 > i) {
#pragma unroll 4
                    for (int jj = 0; jj < 64; jj++) {
                        float4 bj = s_cbx[jj];
                        float xx1 = fmaxf(bi.x, bj.x), yy1 = fmaxf(bi.y, bj.y);
                        float xx2 = fminf(bi.z, bj.z), yy2 = fminf(bi.w, bj.w);
                        float w = fmaxf(1e-10f, xx2 - xx1);
                        float h = fmaxf(1e-10f, yy2 - yy1);
                        float inter = w * h;
                        float u = (s + s_car[jj]) - inter;
                        if (inter > 0.6f * u) mask |= (1ull << jj);
                    }
                } else {
#pragma unroll 4
                    for (int jj = 0; jj < 64; jj++) {
                        float4 bj = s_cbx[jj];
                        float xx1 = fmaxf(bi.x, bj.x), yy1 = fmaxf(bi.y, bj.y);
                        float xx2 = fminf(bi.z, bj.z), yy2 = fminf(bi.w, bj.w);
                        float w = fmaxf(1e-10f, xx2 - xx1);
                        float h = fmaxf(1e-10f, yy2 - yy1);
                        float inter = w * h;
                        float u = (s + s_car[jj]) - inter;
                        if (inter > 0.6f * u && (cb * 64 + jj) > i) mask |= (1ull << jj);
                    }
                }
                g_supp[(size_t)i * 48 + cb] = mask;
            }
        }
    }
    gbar();

    // ---------- Phase I: NMS fixpoint (dense chip-wide round 1, solo tail rounds) ----------
    if (t < 47) { s_valid[t] = g_validw[t]; s_S[t] = 0ull; }
    __syncthreads();
    // pass 1: dense S = OR of rows of valid dets
    for (int idx = gtid; idx < 141376; idx += NBLK * NTHR) {
        int i = idx / 47, f = idx - i * 47;
        if ((s_valid[i >> 6] >> (i & 63)) & 1ull) {
            u64 v = g_supp[(size_t)i * 48 + f];
            if (v) atomicOr(&s_S[f], v);
        }
    }
    __syncthreads();
    if (t < 47 && s_S[t]) atomicOr(&g_S[t], s_S[t]);
    gbar();
    // pass 2: dense R over K = valid & ~S (confirmed kept)
    if (t < 47) { s_K[t] = s_valid[t] & ~g_S[t]; s_R[t] = 0ull; }
    __syncthreads();
    for (int idx = gtid; idx < 141376; idx += NBLK * NTHR) {
        int i = idx / 47, f = idx - i * 47;
        if ((s_K[i >> 6] >> (i & 63)) & 1ull) {
            u64 v = g_supp[(size_t)i * 48 + f];
            if (v) atomicOr(&s_R[f], v);
        }
    }
    __syncthreads();
    if (t < 47 && s_R[t]) atomicOr(&g_R[t], s_R[t]);
    gbar();
    if (bl != 0) return;

    // block 0: finish fixpoint solo
    if (t < 47) {
        s_kept[t] = s_K[t];
        s_alive[t] = s_valid[t] & ~s_K[t] & ~g_R[t];
        g_S[t] = 0ull;                      // clean for next replay
        g_R[t] = 0ull;
        g_validw[t] = 0ull;
    }
    __syncthreads();
    {
        int* list = (int*)sh;               // reuse hist scratch as index list
        while (true) {
            if (t == 0) s_cnt = 0;
            if (t < 47) s_S[t] = 0ull;
            __syncthreads();
            if (t < 47) {
                u64 m = s_alive[t];
                while (m) {
                    int b = __ffsll((long long)m) - 1;
                    m &= m - 1ull;
                    list[atomicAdd(&s_cnt, 1)] = t * 64 + b;
                }
            }
            __syncthreads();
            int n = s_cnt;
            if (n == 0) break;
            for (int p = t; p < n * 47; p += NTHR) {
                int k = p / 47, f = p - k * 47;
                u64 v = g_supp[(size_t)list[k] * 48 + f];
                if (v) atomicOr(&s_S[f], v);
            }
            __syncthreads();
            if (t == 0) s_cnt = 0;
            if (t < 47) {
                u64 K = s_alive[t] & ~s_S[t];
                s_K[t] = K;
                s_kept[t] |= K;
                s_alive[t] &= ~K;
                s_R[t] = 0ull;
            }
            __syncthreads();
            if (t < 47) {
                u64 m = s_K[t];
                while (m) {
                    int b = __ffsll((long long)m) - 1;
                    m &= m - 1ull;
                    list[atomicAdd(&s_cnt, 1)] = t * 64 + b;
                }
            }
            __syncthreads();
            int nk = s_cnt;
            for (int p = t; p < nk * 47; p += NTHR) {
                int k = p / 47, f = p - k * 47;
                u64 v = g_supp[(size_t)list[k] * 48 + f];
                if (v) atomicOr(&s_R[f], v);
            }
            __syncthreads();
            if (t < 47) s_alive[t] &= ~s_R[t];
            __syncthreads();
        }
    }
    // ---------- outputs ----------
    for (int r = t; r < 3000; r += NTHR) {
        int kept = (int)((s_kept[r >> 6] >> (r & 63)) & 1ull);
        out[18000 + g_sorder[r]] = kept ? 1.0f : 0.0f;
    }
}

// ---------------- launch ----------------
extern "C" void kernel_launch(void* const* d_in, const int* in_sizes, int n_in,
                              void* d_out, int out_size) {
    (void)in_sizes; (void)n_in; (void)out_size;
    const float* c0 = (const float*)d_in[0];
    const float* r0 = (const float*)d_in[1];
    const float* c1 = (const float*)d_in[2];
    const float* r1 = (const float*)d_in[3];
    const float* c2 = (const float*)d_in[4];
    const float* r2 = (const float*)d_in[5];
    const float* sc = (const float*)d_in[6];
    float* out = (float*)d_out;

    k_all<<<NBLK, NTHR>>>(c0, r0, c1, r1, c2, r2, sc, out);
}